// round 10
// baseline (speedup 1.0000x reference)
#include <cuda_runtime.h>
#include <cstdint>

// SoftMaxPlus: out[b, :] = cumsum(softplus(beta * c[b, :]) / beta) along S.
// B=4096 rows, S=8192 cols, fp32.
// CTA-per-row, ticket-balanced (self-resetting), depth-3 smem ring filled by
// 1D TMA bulk copies (32KB/row, one instruction) completed via mbarrier.
// One __syncthreads per row publishes warp totals + row queue + slot reuse.

constexpr int S_LEN    = 8192;
constexpr int NTHREADS = 512;
constexpr int NWARPS   = 16;
constexpr int GROUPS   = 4;      // 4 float4 segments per thread
constexpr int DEPTH    = 3;      // ring depth (rows)
constexpr int QN       = 8;      // row-id queue size (power of 2, > 2*DEPTH)
constexpr int GRID     = 304;    // 152 SMs x 2 CTAs
constexpr int ROW_BYTES = S_LEN * 4;   // 32 KB

__device__ unsigned g_ticket;    // zero-initialized at load; self-resets
__device__ unsigned g_done;

__device__ __forceinline__ uint32_t smem_u32(const void* p)
{
    return (uint32_t)__cvta_generic_to_shared(p);
}

__device__ __forceinline__ void mbar_init(uint32_t mbar, uint32_t count)
{
    asm volatile("mbarrier.init.shared.b64 [%0], %1;" :: "r"(mbar), "r"(count) : "memory");
}

__device__ __forceinline__ void mbar_expect_tx(uint32_t mbar, uint32_t bytes)
{
    asm volatile("mbarrier.arrive.expect_tx.shared.b64 _, [%0], %1;"
                 :: "r"(mbar), "r"(bytes) : "memory");
}

__device__ __forceinline__ void mbar_wait(uint32_t mbar, uint32_t parity)
{
    asm volatile(
        "{\n\t.reg .pred P;\n\t"
        "WAIT_%=: \n\t"
        "mbarrier.try_wait.parity.shared::cta.b64 P, [%0], %1;\n\t"
        "@P bra DONE_%=;\n\t"
        "bra WAIT_%=;\n\t"
        "DONE_%=: \n\t}"
        :: "r"(mbar), "r"(parity) : "memory");
}

__device__ __forceinline__ void tma_bulk_load_row(uint32_t smem_dst, const float* gsrc,
                                                  uint32_t mbar)
{
    asm volatile(
        "cp.async.bulk.shared::cta.global.mbarrier::complete_tx::bytes [%0], [%1], %2, [%3];"
        :: "r"(smem_dst), "l"(gsrc), "r"((uint32_t)ROW_BYTES), "r"(mbar) : "memory");
}

// softplus(beta*c)/beta = max(c,0) + log2(1 + exp2(kE*|c|)) * kL
__device__ __forceinline__ float sp_fast(float c, float kE, float kL)
{
    float t = exp2f(kE * fabsf(c));
    return fmaxf(c, 0.0f) + __log2f(1.0f + t) * kL;
}

extern __shared__ float ring[];            // DEPTH * S_LEN floats (96 KB)

__global__ __launch_bounds__(NTHREADS, 2)
void softmaxplus_scan_kernel(const float* __restrict__ c,
                             const float* __restrict__ beta_ptr,
                             float* __restrict__ out,
                             int nrows)
{
    __shared__ unsigned rowq[QN];
    __shared__ float    tot[2][NWARPS];
    __shared__ alignas(8) uint64_t mbar_store[DEPTH];

    const int t = threadIdx.x;
    const int w = t >> 5;
    const int l = t & 31;

    const float beta = __ldg(beta_ptr);
    const float kE = -beta * 1.4426950408889634f;    // -beta*log2(e)
    const float kL = 0.6931471805599453f / beta;     // ln2/beta

    const uint32_t mbar0 = smem_u32(&mbar_store[0]);

    // ---- prologue: init barriers, pull DEPTH tickets, issue DEPTH TMA loads ----
    if (t == 0) {
#pragma unroll
        for (int d = 0; d < DEPTH; d++) mbar_init(mbar0 + d * 8, 1);
#pragma unroll
        for (int d = 0; d < DEPTH; d++) rowq[d] = atomicAdd(&g_ticket, 1u);
    }
    __syncthreads();
    if (t == 0) {
#pragma unroll
        for (int d = 0; d < DEPTH; d++) {
            const unsigned rr = rowq[d];
            if (rr < (unsigned)nrows) {
                mbar_expect_tx(mbar0 + d * 8, ROW_BYTES);
                tma_bulk_load_row(smem_u32(ring + d * S_LEN), c + (long long)rr * S_LEN,
                                  mbar0 + d * 8);
            }
        }
    }
    __syncthreads();   // rowq visible to all before loop

    int it = 0;
    for (;;) {
        const unsigned row = rowq[it & (QN - 1)];
        if (row >= (unsigned)nrows) break;

        const int slot = it % DEPTH;
        mbar_wait(mbar0 + slot * 8, (unsigned)(it / DEPTH) & 1u);

        const float* sbuf = ring + slot * S_LEN;

        // ---- read own 16 floats from smem ----
        float4 vv[GROUPS];
#pragma unroll
        for (int g = 0; g < GROUPS; g++)
            vv[g] = *reinterpret_cast<const float4*>(sbuf + ((w * GROUPS + g) * 32 + l) * 4);

        // pull next ticket (published by this iteration's barrier)
        if (t == 0) rowq[(it + DEPTH) & (QN - 1)] = atomicAdd(&g_ticket, 1u);

        // ---- elementwise + per-thread prefix + segment warp scans ----
        float p[GROUPS][4], texcl[GROUPS], gtot[GROUPS];
#pragma unroll
        for (int g = 0; g < GROUPS; g++) {
            float f0 = sp_fast(vv[g].x, kE, kL);
            float f1 = sp_fast(vv[g].y, kE, kL);
            float f2 = sp_fast(vv[g].z, kE, kL);
            float f3 = sp_fast(vv[g].w, kE, kL);
            p[g][0] = f0;
            p[g][1] = p[g][0] + f1;
            p[g][2] = p[g][1] + f2;
            p[g][3] = p[g][2] + f3;
            float ws = p[g][3];
#pragma unroll
            for (int o = 1; o < 32; o <<= 1) {
                float y = __shfl_up_sync(0xFFFFFFFFu, ws, o);
                if (l >= o) ws += y;
            }
            texcl[g] = ws - p[g][3];
            gtot[g]  = __shfl_sync(0xFFFFFFFFu, ws, 31);
        }

        const float ge1 = gtot[0];
        const float ge2 = ge1 + gtot[1];
        const float ge3 = ge2 + gtot[2];
        const float wtot = ge3 + gtot[3];

        float* tb = tot[it & 1];
        if (l == 0) tb[w] = wtot;
        __syncthreads();   // publishes warp totals + rowq; all LDS of slot done

        // refill the consumed slot for the row DEPTH ahead (single TMA)
        if (t == 0) {
            const unsigned rn = rowq[(it + DEPTH) & (QN - 1)];
            if (rn < (unsigned)nrows) {
                mbar_expect_tx(mbar0 + slot * 8, ROW_BYTES);
                tma_bulk_load_row(smem_u32(ring + slot * S_LEN),
                                  c + (long long)rn * S_LEN, mbar0 + slot * 8);
            }
        }

        // exclusive sum of warp totals for warps < w (masked butterfly)
        float m = (l < w) ? tb[l] : 0.0f;
#pragma unroll
        for (int o = 16; o >= 1; o >>= 1)
            m += __shfl_xor_sync(0xFFFFFFFFu, m, o);

        const float offs[GROUPS] = {m, m + ge1, m + ge2, m + ge3};

        float* rowout = out + (long long)row * S_LEN;
#pragma unroll
        for (int g = 0; g < GROUPS; g++) {
            const float o = offs[g] + texcl[g];
            float4 r = make_float4(p[g][0] + o, p[g][1] + o, p[g][2] + o, p[g][3] + o);
            __stcs(reinterpret_cast<float4*>(rowout + ((w * GROUPS + g) * 32 + l) * 4), r);
        }

        it++;
    }

    // ---- self-reset of the global ticket (removes the reset kernel launch) ----
    if (t == 0) {
        __threadfence();
        unsigned d = atomicAdd(&g_done, 1u);
        if (d == (unsigned)gridDim.x - 1u) {
            g_ticket = 0u;
            g_done   = 0u;
            __threadfence();
        }
    }
}

extern "C" void kernel_launch(void* const* d_in, const int* in_sizes, int n_in,
                              void* d_out, int out_size)
{
    const float* c    = (const float*)d_in[0];
    const float* beta = (const float*)d_in[1];
    float* out        = (float*)d_out;

    const int nrows = in_sizes[0] / S_LEN;   // 4096
    const int smem_bytes = DEPTH * S_LEN * sizeof(float);  // 96 KB

    static bool attr_set = false;
    if (!attr_set) {
        cudaFuncSetAttribute(softmaxplus_scan_kernel,
                             cudaFuncAttributeMaxDynamicSharedMemorySize, smem_bytes);
        attr_set = true;
    }

    softmaxplus_scan_kernel<<<GRID, NTHREADS, smem_bytes>>>(c, beta, out, nrows);
}

// round 11
// speedup vs baseline: 1.2198x; 1.2198x over previous
#include <cuda_runtime.h>

// SoftMaxPlus: out[b, :] = cumsum(softplus(beta * c[b, :]) / beta) along S.
// B=4096 rows, S=8192 cols, fp32.
// CTA-per-row, ticket-balanced (self-resetting), depth-3 per-thread cp.async
// ring with cross-row fetch-ahead. One __syncthreads per row.
// softplus tail uses a degree-4 polynomial for log2(1+u) (u=exp2(kE|c|)):
// only ONE MUFU (EX2) per element instead of two.

constexpr int S_LEN    = 8192;
constexpr int NTHREADS = 512;
constexpr int NWARPS   = 16;
constexpr int GROUPS   = 4;      // 4 float4 segments per thread
constexpr int DEPTH    = 3;      // ring depth (rows)
constexpr int QN       = 8;      // row-id queue size (power of 2, > 2*DEPTH)
constexpr int GRID     = 304;    // 152 SMs x 2 CTAs

__device__ unsigned g_ticket;    // zero at load; self-resets each run
__device__ unsigned g_done;

__device__ __forceinline__ void cp16(float* smem_dst, const float* gsrc)
{
    unsigned s = (unsigned)__cvta_generic_to_shared(smem_dst);
    asm volatile("cp.async.cg.shared.global [%0], [%1], 16;\n" :: "r"(s), "l"(gsrc));
}

// Prefetch one full row into a ring slot. Always commits exactly one group.
__device__ __forceinline__ void prefetch_row(float* slot, const float* __restrict__ c,
                                             unsigned row, int nrows, int w, int l)
{
    if (row < (unsigned)nrows) {
        const float* src = c + (long long)row * S_LEN;
#pragma unroll
        for (int g = 0; g < GROUPS; g++) {
            const int idx = ((w * GROUPS + g) * 32 + l) * 4;
            cp16(slot + idx, src + idx);
        }
    }
    asm volatile("cp.async.commit_group;\n" ::: "memory");
}

// softplus(beta*c)/beta = max(c,0) + log2(1 + exp2(kE*|c|)) * kL,
// with log2(1+u) ~ ((Q4*u + Q3)*u + Q2)*u + Q1)*u  (deg-4, nodes {0,.25,.5,.75,1},
// max abs err ~2e-4). Coefficients arrive pre-multiplied by kL.
__device__ __forceinline__ float sp_fast(float c, float kE,
                                         float A, float B, float C, float D)
{
    float u = exp2f(kE * fabsf(c));                    // FMUL + MUFU.EX2
    float p = fmaf(fmaf(fmaf(fmaf(A, u, B), u, C), u, D), u, 0.0f);
    return fmaxf(c, 0.0f) + p;                         // FMNMX + FADD
}

extern __shared__ float ring[];            // DEPTH * S_LEN floats (96 KB)

__global__ __launch_bounds__(NTHREADS, 2)
void softmaxplus_scan_kernel(const float* __restrict__ c,
                             const float* __restrict__ beta_ptr,
                             float* __restrict__ out,
                             int nrows)
{
    __shared__ unsigned rowq[QN];
    __shared__ float    tot[2][NWARPS];

    const int t = threadIdx.x;
    const int w = t >> 5;
    const int l = t & 31;

    const float beta = __ldg(beta_ptr);
    const float kE = -beta * 1.4426950408889634f;    // -beta*log2(e)
    const float kL = 0.6931471805599453f / beta;     // ln2/beta
    // deg-4 interp of log2(1+u) on [0,1], folded with kL:
    const float A = -0.07847512f * kL;
    const float B =  0.31239740f * kL;
    const float C = -0.67111465f * kL;
    const float D =  1.43719237f * kL;

    // ---- prologue: pull DEPTH tickets, publish, fill the ring ----
    if (t == 0) {
#pragma unroll
        for (int d = 0; d < DEPTH; d++) rowq[d] = atomicAdd(&g_ticket, 1u);
    }
    __syncthreads();
#pragma unroll
    for (int d = 0; d < DEPTH; d++)
        prefetch_row(ring + d * S_LEN, c, rowq[d], nrows, w, l);

    int it = 0;
    for (;;) {
        const unsigned row = rowq[it & (QN - 1)];    // published >= DEPTH iters ago
        if (row >= (unsigned)nrows) {
            asm volatile("cp.async.wait_all;\n" ::: "memory");
            break;
        }

        asm volatile("cp.async.wait_group %0;\n" :: "n"(DEPTH - 1) : "memory");

        const int slot = it % DEPTH;
        const float* sbuf = ring + slot * S_LEN;

        // ---- read own 16 floats from smem ----
        float4 vv[GROUPS];
#pragma unroll
        for (int g = 0; g < GROUPS; g++)
            vv[g] = *reinterpret_cast<const float4*>(sbuf + ((w * GROUPS + g) * 32 + l) * 4);

        // pull next ticket (published by this iteration's barrier)
        if (t == 0) rowq[(it + DEPTH) & (QN - 1)] = atomicAdd(&g_ticket, 1u);

        // ---- elementwise + per-thread prefix + segment warp scans ----
        float p[GROUPS][4], texcl[GROUPS], gtot[GROUPS];
#pragma unroll
        for (int g = 0; g < GROUPS; g++) {
            float f0 = sp_fast(vv[g].x, kE, A, B, C, D);
            float f1 = sp_fast(vv[g].y, kE, A, B, C, D);
            float f2 = sp_fast(vv[g].z, kE, A, B, C, D);
            float f3 = sp_fast(vv[g].w, kE, A, B, C, D);
            p[g][0] = f0;
            p[g][1] = p[g][0] + f1;
            p[g][2] = p[g][1] + f2;
            p[g][3] = p[g][2] + f3;
            float ws = p[g][3];
#pragma unroll
            for (int o = 1; o < 32; o <<= 1) {
                float y = __shfl_up_sync(0xFFFFFFFFu, ws, o);
                if (l >= o) ws += y;
            }
            texcl[g] = ws - p[g][3];
            gtot[g]  = __shfl_sync(0xFFFFFFFFu, ws, 31);
        }

        const float ge1 = gtot[0];
        const float ge2 = ge1 + gtot[1];
        const float ge3 = ge2 + gtot[2];
        const float wtot = ge3 + gtot[3];

        float* tb = tot[it & 1];
        if (l == 0) tb[w] = wtot;
        __syncthreads();   // publishes warp totals AND the new rowq entry

        // refill the consumed slot for the row fetched DEPTH ahead
        prefetch_row(ring + slot * S_LEN, c, rowq[(it + DEPTH) & (QN - 1)], nrows, w, l);

        // exclusive sum of warp totals for warps < w (masked butterfly)
        float m = (l < w) ? tb[l] : 0.0f;
#pragma unroll
        for (int o = 16; o >= 1; o >>= 1)
            m += __shfl_xor_sync(0xFFFFFFFFu, m, o);

        const float offs[GROUPS] = {m, m + ge1, m + ge2, m + ge3};

        float* rowout = out + (long long)row * S_LEN;
#pragma unroll
        for (int g = 0; g < GROUPS; g++) {
            const float o = offs[g] + texcl[g];
            float4 r = make_float4(p[g][0] + o, p[g][1] + o, p[g][2] + o, p[g][3] + o);
            __stcs(reinterpret_cast<float4*>(rowout + ((w * GROUPS + g) * 32 + l) * 4), r);
        }

        it++;
    }

    // ---- self-reset of the global ticket (no extra launch in the graph) ----
    if (t == 0) {
        __threadfence();
        unsigned d = atomicAdd(&g_done, 1u);
        if (d == (unsigned)gridDim.x - 1u) {
            g_ticket = 0u;
            g_done   = 0u;
            __threadfence();
        }
    }
}

extern "C" void kernel_launch(void* const* d_in, const int* in_sizes, int n_in,
                              void* d_out, int out_size)
{
    const float* c    = (const float*)d_in[0];
    const float* beta = (const float*)d_in[1];
    float* out        = (float*)d_out;

    const int nrows = in_sizes[0] / S_LEN;   // 4096
    const int smem_bytes = DEPTH * S_LEN * sizeof(float);  // 96 KB

    static bool attr_set = false;
    if (!attr_set) {
        cudaFuncSetAttribute(softmaxplus_scan_kernel,
                             cudaFuncAttributeMaxDynamicSharedMemorySize, smem_bytes);
        attr_set = true;
    }

    softmaxplus_scan_kernel<<<GRID, NTHREADS, smem_bytes>>>(c, beta, out, nrows);
}